// round 16
// baseline (speedup 1.0000x reference)
#include <cuda_runtime.h>
#include <cuda_fp16.h>
#include <math.h>
#include <stdint.h>

#define BB   512
#define LL   256
#define HH   512
#define AD   128
#define CD   512
#define G4H  2048      // 4*H
#define BH   (BB*HH)   // 262144

// ---------------- fp32 device scratch ----------------
__device__ alignas(16) float g_gates[BB * G4H];     // 4 MB
__device__ alignas(16) float g_vbias[G4H];
__device__ alignas(16) float g_atth[BB * AD];
__device__ alignas(16) float g_scores[BB * LL];

// ---------------- fp16 buffers ----------------
__device__ alignas(16) __half g_wih0h[2048 * 1536];
__device__ alignas(16) __half g_whh0h[2048 * 512];
__device__ alignas(16) __half g_wih1h[2048 * 1024];
__device__ alignas(16) __half g_whh1h[2048 * 512];
__device__ alignas(16) __half g_wih2h[2048 * 1024];
__device__ alignas(16) __half g_whh2h[2048 * 512];
__device__ alignas(16) __half g_wch[128 * 512];
__device__ alignas(16) __half g_cliph[(size_t)BB * LL * CD];   // 67 MB
__device__ alignas(16) __half g_xth[BB * 512];
__device__ alignas(16) __half g_eventh[BB * 512];
__device__ alignas(16) __half g_sh0h[BH];
__device__ alignas(16) __half g_sh1h[BH];
__device__ alignas(16) __half g_sh2h[BH];
__device__ alignas(16) __half g_h0h[BH];
__device__ alignas(16) __half g_h1h[BH];
__device__ alignas(16) __half g_attresh[BB * CD];

__device__ __forceinline__ float sigf(float x) { return 1.0f / (1.0f + expf(-x)); }

__device__ __forceinline__ float tanh_ap(float x) {
    float y;
    asm("tanh.approx.f32 %0, %1;" : "=f"(y) : "f"(x));
    return y;
}

// D += A*B, m16n8k16 fp16 inputs, fp32 accumulate
__device__ __forceinline__ void mma16(float* c, const uint32_t* a, const uint32_t* b) {
    asm volatile("mma.sync.aligned.m16n8k16.row.col.f32.f16.f16.f32 "
        "{%0,%1,%2,%3}, {%4,%5,%6,%7}, {%8,%9}, {%0,%1,%2,%3};"
        : "+f"(c[0]), "+f"(c[1]), "+f"(c[2]), "+f"(c[3])
        : "r"(a[0]), "r"(a[1]), "r"(a[2]), "r"(a[3]), "r"(b[0]), "r"(b[1]));
}

__device__ __forceinline__ void ldsm4(uint32_t* r, uint32_t saddr) {
    asm volatile("ldmatrix.sync.aligned.m8n8.x4.shared.b16 {%0,%1,%2,%3}, [%4];"
        : "=r"(r[0]), "=r"(r[1]), "=r"(r[2]), "=r"(r[3]) : "r"(saddr));
}

__device__ __forceinline__ uint32_t smaddr(const void* p) {
    return (uint32_t)__cvta_generic_to_shared(p);
}
__device__ __forceinline__ void cp16(uint32_t dst, const void* src) {
    asm volatile("cp.async.cg.shared.global [%0], [%1], 16;" :: "r"(dst), "l"(src));
}
__device__ __forceinline__ void cp_commit() { asm volatile("cp.async.commit_group;"); }
template<int N> __device__ __forceinline__ void cp_wait() {
    asm volatile("cp.async.wait_group %0;" :: "n"(N));
}

// ---------------- single-launch fp32 -> fp16 conversion over 13 segments ----------------
__global__ void k_f2h_all(const float* s0, const float* s1, const float* s2,
                          const float* s3, const float* s4, const float* s5,
                          const float* s6, const float* s7, const float* s8,
                          const float* s9, const float* s10, const float* s11,
                          const float* s12) {
    long long q = (long long)blockIdx.x * 256 + threadIdx.x;
    const float* src;
    __half* dst;
    long long i;
    if (q < 786432)            { src = s0;  dst = g_wih0h;  i = q; }
    else if (q < 1048576)      { src = s1;  dst = g_whh0h;  i = q - 786432; }
    else if (q < 1572864)      { src = s2;  dst = g_wih1h;  i = q - 1048576; }
    else if (q < 1835008)      { src = s3;  dst = g_whh1h;  i = q - 1572864; }
    else if (q < 2359296)      { src = s4;  dst = g_wih2h;  i = q - 1835008; }
    else if (q < 2621440)      { src = s5;  dst = g_whh2h;  i = q - 2359296; }
    else if (q < 2637824)      { src = s6;  dst = g_wch;    i = q - 2621440; }
    else if (q < 19415040)     { src = s7;  dst = g_cliph;  i = q - 2637824; }
    else if (q < 19480576)     { src = s8;  dst = g_xth;    i = q - 19415040; }
    else if (q < 19546112)     { src = s9;  dst = g_eventh; i = q - 19480576; }
    else if (q < 19611648)     { src = s10; dst = g_sh0h;   i = q - 19546112; }
    else if (q < 19677184)     { src = s11; dst = g_sh1h;   i = q - 19611648; }
    else                       { src = s12; dst = g_sh2h;   i = q - 19677184; }
    float4 v = reinterpret_cast<const float4*>(src)[i];
    __half2 h0 = __floats2half2_rn(v.x, v.y);
    __half2 h1 = __floats2half2_rn(v.z, v.w);
    uint2 o;
    o.x = *reinterpret_cast<uint32_t*>(&h0);
    o.y = *reinterpret_cast<uint32_t*>(&h1);
    reinterpret_cast<uint2*>(dst)[i] = o;
}
#define F2H_ALL_BLOCKS 77120

// ---------------- layer-0 bias: one warp per n, coalesced (fp32)
__global__ void k_vbias(const float* __restrict__ video,
                        const float* __restrict__ w_ih0,
                        const float* __restrict__ b_ih0,
                        const float* __restrict__ b_hh0) {
    int warp = (blockIdx.x * blockDim.x + threadIdx.x) >> 5;
    int lane = threadIdx.x & 31;
    if (warp >= G4H) return;
    const float* w = w_ih0 + (size_t)warp * 1536 + 512;
    float acc = 0.0f;
    #pragma unroll
    for (int i = 0; i < 16; i++) {
        int k = i * 32 + lane;
        acc += video[k] * w[k];
    }
    #pragma unroll
    for (int o = 16; o > 0; o >>= 1)
        acc += __shfl_xor_sync(0xffffffff, acc, o);
    if (lane == 0) g_vbias[warp] = acc + b_ih0[warp] + b_hh0[warp];
}

// ====== fp16 3-pair NT GEMM: g_gates = sum_p A_p @ W_p^T + bias (R14, unchanged) ======
__device__ __forceinline__ void gemm_pair_h(
    const __half* __restrict__ Ap, int lda,
    const __half* __restrict__ Wp, int ldw,
    int m0, int n0, int tid, int lane, int wm, int wn,
    __half* As, __half* Bs, float acc[2][4][4])
{
    int lrow = tid >> 1;                 // 0..63
    int kh   = (tid & 1) * 16;           // half-offset 0 or 16
    const __half* apg = Ap + (size_t)(m0 + lrow) * lda + kh;
    const __half* bpg = Wp + (size_t)(n0 + lrow) * ldw + kh;
    uint32_t sa = smaddr(As + lrow * 40 + kh);
    uint32_t sb = smaddr(Bs + lrow * 40 + kh);
    const uint32_t SBY = 64 * 40 * 2;    // 5120 B per stage

    uint32_t aoff[2], boff[2];
    {
        int arow = lane & 15, akb = lane >> 4;
        #pragma unroll
        for (int mt = 0; mt < 2; mt++)
            aoff[mt] = (uint32_t)(((wm + mt * 16 + arow) * 40 + akb * 8) * 2);
        int bn = (lane & 7) + ((lane >> 4) << 3), bkb = (lane >> 3) & 1;
        #pragma unroll
        for (int nt = 0; nt < 2; nt++)
            boff[nt] = (uint32_t)(((wn + nt * 16 + bn) * 40 + bkb * 8) * 2);
    }
    uint32_t asb = smaddr(As), bsb = smaddr(Bs);

    #pragma unroll
    for (int st = 0; st < 3; st++) {
        int k0 = st * 32;
        cp16(sa + st * SBY, apg + k0);
        cp16(sa + st * SBY + 16, apg + k0 + 8);
        cp16(sb + st * SBY, bpg + k0);
        cp16(sb + st * SBY + 16, bpg + k0 + 8);
        cp_commit();
    }

    int stage = 0;
    for (int s = 0; s < 16; s++) {
        cp_wait<2>();
        __syncthreads();
        uint32_t ab = asb + stage * SBY;
        uint32_t bb = bsb + stage * SBY;
        #pragma unroll
        for (int kk = 0; kk < 2; kk++) {
            uint32_t af[2][4], bq[2][4];
            ldsm4(af[0], ab + aoff[0] + kk * 32);
            ldsm4(af[1], ab + aoff[1] + kk * 32);
            ldsm4(bq[0], bb + boff[0] + kk * 32);
            ldsm4(bq[1], bb + boff[1] + kk * 32);
            #pragma unroll
            for (int mt = 0; mt < 2; mt++)
                #pragma unroll
                for (int j = 0; j < 4; j++)
                    mma16(acc[mt][j], af[mt], &bq[j >> 1][(j & 1) * 2]);
        }
        __syncthreads();
        if (s < 13) {
            int k0 = (s + 3) * 32;
            cp16(sa + stage * SBY, apg + k0);
            cp16(sa + stage * SBY + 16, apg + k0 + 8);
            cp16(sb + stage * SBY, bpg + k0);
            cp16(sb + stage * SBY + 16, bpg + k0 + 8);
        }
        cp_commit();
        stage++; if (stage == 3) stage = 0;
    }
}

__global__ __launch_bounds__(128)
void k_gemm3_h(int layer, const float* __restrict__ bias0,
               const float* __restrict__ bias1, int bias_mode)
{
    __shared__ __half As[3 * 64 * 40];
    __shared__ __half Bs[3 * 64 * 40];
    int tid = threadIdx.x;
    int wid = tid >> 5, lane = tid & 31;
    int m0 = blockIdx.y * 64, n0 = blockIdx.x * 64;
    int wm = (wid >> 1) * 32, wn = (wid & 1) * 32;

    const __half *A0, *A1, *A2, *W0, *W1, *W2;
    int ldw0, ldw1, ldw2;
    if (layer == 0) {
        A0 = g_xth; A1 = g_sh2h; A2 = g_sh0h;
        W0 = g_wih0h; ldw0 = 1536; W1 = g_wih0h + 1024; ldw1 = 1536;
        W2 = g_whh0h; ldw2 = 512;
    } else if (layer == 1) {
        A0 = g_eventh; A1 = g_h0h; A2 = g_sh1h;
        W0 = g_wih1h; ldw0 = 1024; W1 = g_wih1h + 512; ldw1 = 1024;
        W2 = g_whh1h; ldw2 = 512;
    } else {
        A0 = g_attresh; A1 = g_h1h; A2 = g_sh2h;
        W0 = g_wih2h; ldw0 = 1024; W1 = g_wih2h + 512; ldw1 = 1024;
        W2 = g_whh2h; ldw2 = 512;
    }

    float acc[2][4][4];
    #pragma unroll
    for (int i = 0; i < 2; i++)
        #pragma unroll
        for (int j = 0; j < 4; j++)
            #pragma unroll
            for (int k = 0; k < 4; k++) acc[i][j][k] = 0.0f;

    gemm_pair_h(A0, 512, W0, ldw0, m0, n0, tid, lane, wm, wn, As, Bs, acc);
    gemm_pair_h(A1, 512, W1, ldw1, m0, n0, tid, lane, wm, wn, As, Bs, acc);
    gemm_pair_h(A2, 512, W2, ldw2, m0, n0, tid, lane, wm, wn, As, Bs, acc);

    #pragma unroll
    for (int mt = 0; mt < 2; mt++) {
        int r = m0 + wm + mt * 16 + (lane >> 2);
        #pragma unroll
        for (int nt = 0; nt < 4; nt++) {
            int c = n0 + wn + nt * 8 + 2 * (lane & 3);
            float b0, b1;
            if (bias_mode) { b0 = g_vbias[c]; b1 = g_vbias[c + 1]; }
            else           { b0 = bias0[c] + bias1[c]; b1 = bias0[c + 1] + bias1[c + 1]; }
            g_gates[(size_t)r * G4H + c]           = acc[mt][nt][0] + b0;
            g_gates[(size_t)r * G4H + c + 1]       = acc[mt][nt][1] + b1;
            g_gates[(size_t)(r + 8) * G4H + c]     = acc[mt][nt][2] + b0;
            g_gates[(size_t)(r + 8) * G4H + c + 1] = acc[mt][nt][3] + b1;
        }
    }
}

// ---------------- LSTM activation: g_gates -> (h, c); optionally writes fp16 h copy
__global__ void k_lstm_act(const float* __restrict__ cprev,
                           float* __restrict__ hout, float* __restrict__ cout,
                           float* __restrict__ hout2, int hsel) {
    int idx = blockIdx.x * blockDim.x + threadIdx.x;
    if (idx >= BH) return;
    int b = idx / HH, j = idx % HH;
    const float* g = g_gates + (size_t)b * G4H;
    float gi = g[j], gf = g[HH + j], gg = g[2 * HH + j], go = g[3 * HH + j];
    float c = sigf(gf) * cprev[idx] + sigf(gi) * tanhf(gg);
    float h = sigf(go) * tanhf(c);
    hout[idx] = h;
    cout[idx] = c;
    if (hout2) hout2[idx] = h;
    if (hsel == 0) g_h0h[idx] = __float2half_rn(h);
    else if (hsel == 1) g_h1h[idx] = __float2half_rn(h);
}

// ---------------- att_h = h1 @ wh.T + bh  ([B,128], fp32)
__global__ void k_atth(const float* __restrict__ h1, const float* __restrict__ wh,
                       const float* __restrict__ bh) {
    __shared__ float hs[512];
    int b = blockIdx.x, t = threadIdx.x;   // 128 threads
    for (int i = t; i < 512; i += 128) hs[i] = h1[(size_t)b * 512 + i];
    __syncthreads();
    const float* w = wh + (size_t)t * 512;
    float acc = bh[t];
    #pragma unroll 8
    for (int k = 0; k < 512; k++) acc += hs[k] * w[k];
    g_atth[b * AD + t] = acc;
}

// ====== fp16 fused attention scores (R14-validated): 64x128 block, 8 warps, 3-stage ======
__global__ __launch_bounds__(256)
void k_att_h(const float* __restrict__ bc, const float* __restrict__ wa,
             const float* __restrict__ ba) {
    __shared__ __half As[3 * 64 * 40];      // 15360 B
    __shared__ __half Bs[3 * 128 * 40];     // 30720 B
    __shared__ float red[64 * 5];           // 1280 B
    __shared__ float addsh[128], wash[128]; // 1024 B

    int tid = threadIdx.x;
    int wid = tid >> 5, lane = tid & 31;
    int m0 = blockIdx.x * 64;           // row within [B*L]
    int bidx = blockIdx.x >> 2;         // batch (4 blocks per batch)
    int wm = (wid >> 2) * 32;           // 0 or 32
    int wn = (wid & 3) * 32;            // 0,32,64,96

    if (tid < 128) {
        addsh[tid] = bc[tid] + g_atth[bidx * AD + tid];
        wash[tid] = wa[tid];
    }

    // loaders: A 64 rows x 32 halves -> 1 cp16/thr; B 128 rows -> 2 cp16/thr
    int lrowA = tid >> 2;               // 0..63
    int kcA   = (tid & 3) * 8;          // halves 0,8,16,24
    int lrowB = tid >> 1;               // 0..127
    int kcB   = (tid & 1) * 16;         // halves 0 or 16
    const __half* apg = g_cliph + (size_t)(m0 + lrowA) * CD + kcA;
    const __half* bpg = g_wch + (size_t)lrowB * 512 + kcB;
    uint32_t sa = smaddr(As + lrowA * 40 + kcA);
    uint32_t sb = smaddr(Bs + lrowB * 40 + kcB);
    const uint32_t SA = 64 * 40 * 2, SB = 128 * 40 * 2;

    uint32_t aoff[2], boff[2];
    {
        int arow = lane & 15, akb = lane >> 4;
        #pragma unroll
        for (int mt = 0; mt < 2; mt++)
            aoff[mt] = (uint32_t)(((wm + mt * 16 + arow) * 40 + akb * 8) * 2);
        int bn = (lane & 7) + ((lane >> 4) << 3), bkb = (lane >> 3) & 1;
        #pragma unroll
        for (int nt = 0; nt < 2; nt++)
            boff[nt] = (uint32_t)(((wn + nt * 16 + bn) * 40 + bkb * 8) * 2);
    }
    uint32_t asb = smaddr(As), bsb = smaddr(Bs);

    float acc[2][4][4];
    #pragma unroll
    for (int i = 0; i < 2; i++)
        #pragma unroll
        for (int j = 0; j < 4; j++)
            #pragma unroll
            for (int k = 0; k < 4; k++) acc[i][j][k] = 0.0f;

    #pragma unroll
    for (int st = 0; st < 3; st++) {
        int k0 = st * 32;
        cp16(sa + st * SA, apg + k0);
        cp16(sb + st * SB, bpg + k0);
        cp16(sb + st * SB + 16, bpg + k0 + 8);
        cp_commit();
    }

    int stage = 0;
    for (int s = 0; s < 16; s++) {
        cp_wait<2>();
        __syncthreads();
        uint32_t ab = asb + stage * SA;
        uint32_t bb = bsb + stage * SB;
        #pragma unroll
        for (int kk = 0; kk < 2; kk++) {
            uint32_t af[2][4], bq[2][4];
            ldsm4(af[0], ab + aoff[0] + kk * 32);
            ldsm4(af[1], ab + aoff[1] + kk * 32);
            ldsm4(bq[0], bb + boff[0] + kk * 32);
            ldsm4(bq[1], bb + boff[1] + kk * 32);
            #pragma unroll
            for (int mt = 0; mt < 2; mt++)
                #pragma unroll
                for (int j = 0; j < 4; j++)
                    mma16(acc[mt][j], af[mt], &bq[j >> 1][(j & 1) * 2]);
        }
        __syncthreads();
        if (s < 13) {
            int k0 = (s + 3) * 32;
            cp16(sa + stage * SA, apg + k0);
            cp16(sb + stage * SB, bpg + k0);
            cp16(sb + stage * SB + 16, bpg + k0 + 8);
        }
        cp_commit();
        stage++; if (stage == 3) stage = 0;
    }

    // epilogue: HW tanh + dot with wa; in-quad shuffle, then cross-n-warp reduce
    float ps[2][2] = {{0.0f, 0.0f}, {0.0f, 0.0f}};
    #pragma unroll
    for (int mt = 0; mt < 2; mt++) {
        #pragma unroll
        for (int nt = 0; nt < 4; nt++) {
            int c = wn + nt * 8 + 2 * (lane & 3);
            float a0 = addsh[c], a1 = addsh[c + 1];
            float w0 = wash[c], w1 = wash[c + 1];
            float t0 = tanh_ap(acc[mt][nt][0] + a0);
            float t1 = tanh_ap(acc[mt][nt][1] + a1);
            float t2 = tanh_ap(acc[mt][nt][2] + a0);
            float t3 = tanh_ap(acc[mt][nt][3] + a1);
            ps[mt][0] += t0 * w0 + t1 * w1;
            ps[mt][1] += t2 * w0 + t3 * w1;
        }
    }
    #pragma unroll
    for (int o = 1; o <= 2; o <<= 1) {
        ps[0][0] += __shfl_xor_sync(0xffffffff, ps[0][0], o);
        ps[0][1] += __shfl_xor_sync(0xffffffff, ps[0][1], o);
        ps[1][0] += __shfl_xor_sync(0xffffffff, ps[1][0], o);
        ps[1][1] += __shfl_xor_sync(0xffffffff, ps[1][1], o);
    }
    if ((lane & 3) == 0) {
        int wq = wid & 3;
        int lq = lane >> 2;
        #pragma unroll
        for (int mt = 0; mt < 2; mt++) {
            int r = wm + mt * 16 + lq;
            red[r * 5 + wq] = ps[mt][0];
            red[(r + 8) * 5 + wq] = ps[mt][1];
        }
    }
    __syncthreads();
    if (tid < 64) {
        g_scores[m0 + tid] = ba[0] + red[tid * 5] + red[tid * 5 + 1]
                           + red[tid * 5 + 2] + red[tid * 5 + 3];
    }
}

// ---------------- fused masked softmax + att_res (one block per batch, 256 thr)
__global__ void k_soft_attres(const int* __restrict__ mask) {
    __shared__ float sh[256];
    __shared__ float w[256];
    __shared__ float part[512];
    int b = blockIdx.x, t = threadIdx.x;
    float s = g_scores[b * LL + t];
    sh[t] = s;
    __syncthreads();
    for (int o = 128; o > 0; o >>= 1) {
        if (t < o) sh[t] = fmaxf(sh[t], sh[t + o]);
        __syncthreads();
    }
    float mx = sh[0];
    __syncthreads();
    float p = expf(s - mx);
    float pm = p * (float)mask[b * LL + t];
    sh[t] = pm;
    __syncthreads();
    for (int o = 128; o > 0; o >>= 1) {
        if (t < o) sh[t] += sh[t + o];
        __syncthreads();
    }
    float denom = sh[0];
    w[t] = pm / denom;
    __syncthreads();

    int half_ = t >> 7, tt = t & 127;
    const __half* cb = g_cliph + (size_t)b * LL * CD + (size_t)half_ * 128 * CD;
    const float* wl = w + half_ * 128;
    float a0 = 0.0f, a1 = 0.0f, a2 = 0.0f, a3 = 0.0f;
    #pragma unroll 4
    for (int l = 0; l < 128; l++) {
        float wv = wl[l];
        uint2 u = *reinterpret_cast<const uint2*>(cb + (size_t)l * CD + tt * 4);
        __half2 h0 = *reinterpret_cast<__half2*>(&u.x);
        __half2 h1 = *reinterpret_cast<__half2*>(&u.y);
        float2 f0 = __half22float2(h0);
        float2 f1 = __half22float2(h1);
        a0 += wv * f0.x; a1 += wv * f0.y; a2 += wv * f1.x; a3 += wv * f1.y;
    }
    if (half_) {
        part[tt * 4] = a0; part[tt * 4 + 1] = a1; part[tt * 4 + 2] = a2; part[tt * 4 + 3] = a3;
    }
    __syncthreads();
    if (!half_) {
        a0 += part[tt * 4]; a1 += part[tt * 4 + 1]; a2 += part[tt * 4 + 2]; a3 += part[tt * 4 + 3];
        __half2 h0 = __floats2half2_rn(a0, a1);
        __half2 h1 = __floats2half2_rn(a2, a3);
        uint2 o;
        o.x = *reinterpret_cast<uint32_t*>(&h0);
        o.y = *reinterpret_cast<uint32_t*>(&h1);
        *reinterpret_cast<uint2*>(&g_attresh[b * CD + tt * 4]) = o;
    }
}

// ---------------- launch ----------------
extern "C" void kernel_launch(void* const* d_in, const int* in_sizes, int n_in,
                              void* d_out, int out_size) {
    const float* xt      = (const float*)d_in[0];
    const float* video   = (const float*)d_in[1];
    const float* event   = (const float*)d_in[2];
    const float* clip    = (const float*)d_in[3];
    const int*   cmask   = (const int*)d_in[4];
    const float* state_h = (const float*)d_in[5];
    const float* state_c = (const float*)d_in[6];
    const float* w_ih0   = (const float*)d_in[7];
    const float* w_hh0   = (const float*)d_in[8];
    const float* b_ih0   = (const float*)d_in[9];
    const float* b_hh0   = (const float*)d_in[10];
    const float* w_ih1   = (const float*)d_in[11];
    const float* w_hh1   = (const float*)d_in[12];
    const float* b_ih1   = (const float*)d_in[13];
    const float* b_hh1   = (const float*)d_in[14];
    const float* w_ih2   = (const float*)d_in[15];
    const float* w_hh2   = (const float*)d_in[16];
    const float* b_ih2   = (const float*)d_in[17];
    const float* b_hh2   = (const float*)d_in[18];
    const float* wc      = (const float*)d_in[19];
    const float* bc      = (const float*)d_in[20];
    const float* wh      = (const float*)d_in[21];
    const float* bh      = (const float*)d_in[22];
    const float* wa      = (const float*)d_in[23];
    const float* ba      = (const float*)d_in[24];

    float* out = (float*)d_out;
    float* h2o = out;            // h2: [B,H]
    float* nh  = out + BH;       // new_h: 3 x [B,H]
    float* nc  = out + 4 * BH;   // new_c: 3 x [B,H]

    // all fp32->fp16 conversions in ONE launch
    k_f2h_all<<<F2H_ALL_BLOCKS, 256>>>(w_ih0, w_hh0, w_ih1, w_hh1, w_ih2, w_hh2,
                                       wc, clip, xt, event,
                                       state_h, state_h + BH, state_h + 2 * BH);
    k_vbias<<<(G4H * 32) / 256, 256>>>(video, w_ih0, b_ih0, b_hh0);

    dim3 ggrid(G4H / 64, BB / 64);   // (32, 8)

    // layer 0
    k_gemm3_h<<<ggrid, 128>>>(0, b_ih0, b_hh0, /*bias_mode=*/1);
    k_lstm_act<<<BH / 256, 256>>>(state_c, nh, nc, nullptr, /*hsel=*/0);

    // layer 1
    k_gemm3_h<<<ggrid, 128>>>(1, b_ih1, b_hh1, 0);
    k_lstm_act<<<BH / 256, 256>>>(state_c + BH, nh + BH, nc + BH, nullptr, /*hsel=*/1);

    // attention
    k_atth<<<BB, 128>>>(nh + BH, wh, bh);
    k_att_h<<<(BB * LL) / 64, 256>>>(bc, wa, ba);
    k_soft_attres<<<BB, 256>>>(cmask);

    // layer 2
    k_gemm3_h<<<ggrid, 128>>>(2, b_ih2, b_hh2, 0);
    k_lstm_act<<<BH / 256, 256>>>(state_c + 2 * BH, nh + 2 * BH, nc + 2 * BH, h2o, /*hsel=*/2);
}

// round 17
// speedup vs baseline: 1.1547x; 1.1547x over previous
#include <cuda_runtime.h>
#include <cuda_fp16.h>
#include <math.h>
#include <stdint.h>

#define BB   512
#define LL   256
#define HH   512
#define AD   128
#define CD   512
#define G4H  2048      // 4*H
#define BH   (BB*HH)   // 262144

// ---------------- fp32 device scratch ----------------
__device__ alignas(16) float g_gates[BB * G4H];     // 4 MB
__device__ alignas(16) float g_vbias[G4H];
__device__ alignas(16) float g_atth[BB * AD];
__device__ alignas(16) float g_scores[BB * LL];

// ---------------- fp16 buffers ----------------
__device__ alignas(16) __half g_wih0h[2048 * 1536];
__device__ alignas(16) __half g_whh0h[2048 * 512];
__device__ alignas(16) __half g_wih1h[2048 * 1024];
__device__ alignas(16) __half g_whh1h[2048 * 512];
__device__ alignas(16) __half g_wih2h[2048 * 1024];
__device__ alignas(16) __half g_whh2h[2048 * 512];
__device__ alignas(16) __half g_wch[128 * 512];
__device__ alignas(16) __half g_cliph[(size_t)BB * LL * CD];   // 67 MB (written by k_att_h)
__device__ alignas(16) __half g_xth[BB * 512];
__device__ alignas(16) __half g_eventh[BB * 512];
__device__ alignas(16) __half g_sh0h[BH];
__device__ alignas(16) __half g_sh1h[BH];
__device__ alignas(16) __half g_sh2h[BH];
__device__ alignas(16) __half g_h0h[BH];
__device__ alignas(16) __half g_h1h[BH];
__device__ alignas(16) __half g_attresh[BB * CD];

__device__ __forceinline__ float sigf(float x) { return 1.0f / (1.0f + expf(-x)); }

__device__ __forceinline__ float tanh_ap(float x) {
    float y;
    asm("tanh.approx.f32 %0, %1;" : "=f"(y) : "f"(x));
    return y;
}

// D += A*B, m16n8k16 fp16 inputs, fp32 accumulate
__device__ __forceinline__ void mma16(float* c, const uint32_t* a, const uint32_t* b) {
    asm volatile("mma.sync.aligned.m16n8k16.row.col.f32.f16.f16.f32 "
        "{%0,%1,%2,%3}, {%4,%5,%6,%7}, {%8,%9}, {%0,%1,%2,%3};"
        : "+f"(c[0]), "+f"(c[1]), "+f"(c[2]), "+f"(c[3])
        : "r"(a[0]), "r"(a[1]), "r"(a[2]), "r"(a[3]), "r"(b[0]), "r"(b[1]));
}

__device__ __forceinline__ void ldsm4(uint32_t* r, uint32_t saddr) {
    asm volatile("ldmatrix.sync.aligned.m8n8.x4.shared.b16 {%0,%1,%2,%3}, [%4];"
        : "=r"(r[0]), "=r"(r[1]), "=r"(r[2]), "=r"(r[3]) : "r"(saddr));
}

__device__ __forceinline__ uint32_t smaddr(const void* p) {
    return (uint32_t)__cvta_generic_to_shared(p);
}
__device__ __forceinline__ void cp16(uint32_t dst, const void* src) {
    asm volatile("cp.async.cg.shared.global [%0], [%1], 16;" :: "r"(dst), "l"(src));
}
__device__ __forceinline__ void cp_commit() { asm volatile("cp.async.commit_group;"); }
template<int N> __device__ __forceinline__ void cp_wait() {
    asm volatile("cp.async.wait_group %0;" :: "n"(N));
}

// ---------------- single-launch fp32 -> fp16 conversion (weights + activations, NO clip)
__global__ void k_f2h_all(const float* s0, const float* s1, const float* s2,
                          const float* s3, const float* s4, const float* s5,
                          const float* s6, const float* s8,
                          const float* s9, const float* s10, const float* s11,
                          const float* s12) {
    int q = blockIdx.x * 256 + threadIdx.x;
    const float* src;
    __half* dst;
    int i;
    if (q < 786432)            { src = s0;  dst = g_wih0h;  i = q; }
    else if (q < 1048576)      { src = s1;  dst = g_whh0h;  i = q - 786432; }
    else if (q < 1572864)      { src = s2;  dst = g_wih1h;  i = q - 1048576; }
    else if (q < 1835008)      { src = s3;  dst = g_whh1h;  i = q - 1572864; }
    else if (q < 2359296)      { src = s4;  dst = g_wih2h;  i = q - 1835008; }
    else if (q < 2621440)      { src = s5;  dst = g_whh2h;  i = q - 2359296; }
    else if (q < 2637824)      { src = s6;  dst = g_wch;    i = q - 2621440; }
    else if (q < 2703360)      { src = s8;  dst = g_xth;    i = q - 2637824; }
    else if (q < 2768896)      { src = s9;  dst = g_eventh; i = q - 2703360; }
    else if (q < 2834432)      { src = s10; dst = g_sh0h;   i = q - 2768896; }
    else if (q < 2899968)      { src = s11; dst = g_sh1h;   i = q - 2834432; }
    else                       { src = s12; dst = g_sh2h;   i = q - 2899968; }
    float4 v = reinterpret_cast<const float4*>(src)[i];
    __half2 h0 = __floats2half2_rn(v.x, v.y);
    __half2 h1 = __floats2half2_rn(v.z, v.w);
    uint2 o;
    o.x = *reinterpret_cast<uint32_t*>(&h0);
    o.y = *reinterpret_cast<uint32_t*>(&h1);
    reinterpret_cast<uint2*>(dst)[i] = o;
}
#define F2H_ALL_BLOCKS 11584   // 2965504/256

// ---------------- layer-0 bias: one warp per n, coalesced (fp32)
__global__ void k_vbias(const float* __restrict__ video,
                        const float* __restrict__ w_ih0,
                        const float* __restrict__ b_ih0,
                        const float* __restrict__ b_hh0) {
    int warp = (blockIdx.x * blockDim.x + threadIdx.x) >> 5;
    int lane = threadIdx.x & 31;
    if (warp >= G4H) return;
    const float* w = w_ih0 + (size_t)warp * 1536 + 512;
    float acc = 0.0f;
    #pragma unroll
    for (int i = 0; i < 16; i++) {
        int k = i * 32 + lane;
        acc += video[k] * w[k];
    }
    #pragma unroll
    for (int o = 16; o > 0; o >>= 1)
        acc += __shfl_xor_sync(0xffffffff, acc, o);
    if (lane == 0) g_vbias[warp] = acc + b_ih0[warp] + b_hh0[warp];
}

// ====== fp16 3-pair NT GEMM: g_gates = sum_p A_p @ W_p^T + bias (R14, unchanged) ======
__device__ __forceinline__ void gemm_pair_h(
    const __half* __restrict__ Ap, int lda,
    const __half* __restrict__ Wp, int ldw,
    int m0, int n0, int tid, int lane, int wm, int wn,
    __half* As, __half* Bs, float acc[2][4][4])
{
    int lrow = tid >> 1;                 // 0..63
    int kh   = (tid & 1) * 16;           // half-offset 0 or 16
    const __half* apg = Ap + (size_t)(m0 + lrow) * lda + kh;
    const __half* bpg = Wp + (size_t)(n0 + lrow) * ldw + kh;
    uint32_t sa = smaddr(As + lrow * 40 + kh);
    uint32_t sb = smaddr(Bs + lrow * 40 + kh);
    const uint32_t SBY = 64 * 40 * 2;    // 5120 B per stage

    uint32_t aoff[2], boff[2];
    {
        int arow = lane & 15, akb = lane >> 4;
        #pragma unroll
        for (int mt = 0; mt < 2; mt++)
            aoff[mt] = (uint32_t)(((wm + mt * 16 + arow) * 40 + akb * 8) * 2);
        int bn = (lane & 7) + ((lane >> 4) << 3), bkb = (lane >> 3) & 1;
        #pragma unroll
        for (int nt = 0; nt < 2; nt++)
            boff[nt] = (uint32_t)(((wn + nt * 16 + bn) * 40 + bkb * 8) * 2);
    }
    uint32_t asb = smaddr(As), bsb = smaddr(Bs);

    #pragma unroll
    for (int st = 0; st < 3; st++) {
        int k0 = st * 32;
        cp16(sa + st * SBY, apg + k0);
        cp16(sa + st * SBY + 16, apg + k0 + 8);
        cp16(sb + st * SBY, bpg + k0);
        cp16(sb + st * SBY + 16, bpg + k0 + 8);
        cp_commit();
    }

    int stage = 0;
    for (int s = 0; s < 16; s++) {
        cp_wait<2>();
        __syncthreads();
        uint32_t ab = asb + stage * SBY;
        uint32_t bb = bsb + stage * SBY;
        #pragma unroll
        for (int kk = 0; kk < 2; kk++) {
            uint32_t af[2][4], bq[2][4];
            ldsm4(af[0], ab + aoff[0] + kk * 32);
            ldsm4(af[1], ab + aoff[1] + kk * 32);
            ldsm4(bq[0], bb + boff[0] + kk * 32);
            ldsm4(bq[1], bb + boff[1] + kk * 32);
            #pragma unroll
            for (int mt = 0; mt < 2; mt++)
                #pragma unroll
                for (int j = 0; j < 4; j++)
                    mma16(acc[mt][j], af[mt], &bq[j >> 1][(j & 1) * 2]);
        }
        __syncthreads();
        if (s < 13) {
            int k0 = (s + 3) * 32;
            cp16(sa + stage * SBY, apg + k0);
            cp16(sa + stage * SBY + 16, apg + k0 + 8);
            cp16(sb + stage * SBY, bpg + k0);
            cp16(sb + stage * SBY + 16, bpg + k0 + 8);
        }
        cp_commit();
        stage++; if (stage == 3) stage = 0;
    }
}

__global__ __launch_bounds__(128)
void k_gemm3_h(int layer, const float* __restrict__ bias0,
               const float* __restrict__ bias1, int bias_mode)
{
    __shared__ __half As[3 * 64 * 40];
    __shared__ __half Bs[3 * 64 * 40];
    int tid = threadIdx.x;
    int wid = tid >> 5, lane = tid & 31;
    int m0 = blockIdx.y * 64, n0 = blockIdx.x * 64;
    int wm = (wid >> 1) * 32, wn = (wid & 1) * 32;

    const __half *A0, *A1, *A2, *W0, *W1, *W2;
    int ldw0, ldw1, ldw2;
    if (layer == 0) {
        A0 = g_xth; A1 = g_sh2h; A2 = g_sh0h;
        W0 = g_wih0h; ldw0 = 1536; W1 = g_wih0h + 1024; ldw1 = 1536;
        W2 = g_whh0h; ldw2 = 512;
    } else if (layer == 1) {
        A0 = g_eventh; A1 = g_h0h; A2 = g_sh1h;
        W0 = g_wih1h; ldw0 = 1024; W1 = g_wih1h + 512; ldw1 = 1024;
        W2 = g_whh1h; ldw2 = 512;
    } else {
        A0 = g_attresh; A1 = g_h1h; A2 = g_sh2h;
        W0 = g_wih2h; ldw0 = 1024; W1 = g_wih2h + 512; ldw1 = 1024;
        W2 = g_whh2h; ldw2 = 512;
    }

    float acc[2][4][4];
    #pragma unroll
    for (int i = 0; i < 2; i++)
        #pragma unroll
        for (int j = 0; j < 4; j++)
            #pragma unroll
            for (int k = 0; k < 4; k++) acc[i][j][k] = 0.0f;

    gemm_pair_h(A0, 512, W0, ldw0, m0, n0, tid, lane, wm, wn, As, Bs, acc);
    gemm_pair_h(A1, 512, W1, ldw1, m0, n0, tid, lane, wm, wn, As, Bs, acc);
    gemm_pair_h(A2, 512, W2, ldw2, m0, n0, tid, lane, wm, wn, As, Bs, acc);

    #pragma unroll
    for (int mt = 0; mt < 2; mt++) {
        int r = m0 + wm + mt * 16 + (lane >> 2);
        #pragma unroll
        for (int nt = 0; nt < 4; nt++) {
            int c = n0 + wn + nt * 8 + 2 * (lane & 3);
            float b0, b1;
            if (bias_mode) { b0 = g_vbias[c]; b1 = g_vbias[c + 1]; }
            else           { b0 = bias0[c] + bias1[c]; b1 = bias0[c + 1] + bias1[c + 1]; }
            g_gates[(size_t)r * G4H + c]           = acc[mt][nt][0] + b0;
            g_gates[(size_t)r * G4H + c + 1]       = acc[mt][nt][1] + b1;
            g_gates[(size_t)(r + 8) * G4H + c]     = acc[mt][nt][2] + b0;
            g_gates[(size_t)(r + 8) * G4H + c + 1] = acc[mt][nt][3] + b1;
        }
    }
}

// ---------------- LSTM activation (clock canary position in ncu window)
__global__ void k_lstm_act(const float* __restrict__ cprev,
                           float* __restrict__ hout, float* __restrict__ cout,
                           float* __restrict__ hout2, int hsel) {
    int idx = blockIdx.x * blockDim.x + threadIdx.x;
    if (idx >= BH) return;
    int b = idx / HH, j = idx % HH;
    const float* g = g_gates + (size_t)b * G4H;
    float gi = g[j], gf = g[HH + j], gg = g[2 * HH + j], go = g[3 * HH + j];
    float c = sigf(gf) * cprev[idx] + sigf(gi) * tanhf(gg);
    float h = sigf(go) * tanhf(c);
    hout[idx] = h;
    cout[idx] = c;
    if (hout2) hout2[idx] = h;
    if (hsel == 0) g_h0h[idx] = __float2half_rn(h);
    else if (hsel == 1) g_h1h[idx] = __float2half_rn(h);
}

// ---------------- att_h = h1 @ wh.T + bh  ([B,128], fp32)
__global__ void k_atth(const float* __restrict__ h1, const float* __restrict__ wh,
                       const float* __restrict__ bh) {
    __shared__ float hs[512];
    int b = blockIdx.x, t = threadIdx.x;   // 128 threads
    for (int i = t; i < 512; i += 128) hs[i] = h1[(size_t)b * 512 + i];
    __syncthreads();
    const float* w = wh + (size_t)t * 512;
    float acc = bh[t];
    #pragma unroll 8
    for (int k = 0; k < 512; k++) acc += hs[k] * w[k];
    g_atth[b * AD + t] = acc;
}

// ====== fp16 fused attention scores + clip conversion ======
// 64x128 block, 8 warps (2m x 4n), 3-stage. A = fp32 clip converted in regs
// (LDG depth-2 software pipeline), STS to smem AND STG fp16 copy to g_cliph.
// B = g_wch via cp.async (unchanged).
__global__ __launch_bounds__(256)
void k_att_h(const float* __restrict__ clip, const float* __restrict__ bc,
             const float* __restrict__ wa, const float* __restrict__ ba) {
    __shared__ __half As[3 * 64 * 40];      // 15360 B
    __shared__ __half Bs[3 * 128 * 40];     // 30720 B
    __shared__ float red[64 * 5];           // 1280 B
    __shared__ float addsh[128], wash[128]; // 1024 B

    int tid = threadIdx.x;
    int wid = tid >> 5, lane = tid & 31;
    int m0 = blockIdx.x * 64;           // row within [B*L]
    int bidx = blockIdx.x >> 2;         // batch (4 blocks per batch)
    int wm = (wid >> 2) * 32;           // 0 or 32
    int wn = (wid & 3) * 32;            // 0,32,64,96

    if (tid < 128) {
        addsh[tid] = bc[tid] + g_atth[bidx * AD + tid];
        wash[tid] = wa[tid];
    }

    // A loader: fp32 clip, 8 floats (2 float4) per thread per k-chunk of 32
    int lrowA = tid >> 2;               // 0..63
    int kcA   = (tid & 3) * 8;          // 0,8,16,24
    const float* ap32 = clip + (size_t)(m0 + lrowA) * CD + kcA;
    __half* agout = g_cliph + (size_t)(m0 + lrowA) * CD + kcA;
    uint32_t sa = smaddr(As + lrowA * 40 + kcA);
    // B loader: 128 rows x 32 halves -> 2 cp16/thr
    int lrowB = tid >> 1;               // 0..127
    int kcB   = (tid & 1) * 16;         // 0 or 16
    const __half* bpg = g_wch + (size_t)lrowB * 512 + kcB;
    uint32_t sb = smaddr(Bs + lrowB * 40 + kcB);
    const uint32_t SA = 64 * 40 * 2, SB = 128 * 40 * 2;

    float4 ra[2][2];
    #define LDGA(slot, c) do { \
        ra[slot][0] = *reinterpret_cast<const float4*>(ap32 + (c) * 32); \
        ra[slot][1] = *reinterpret_cast<const float4*>(ap32 + (c) * 32 + 4); \
    } while (0)
    #define PUTA(stg, slot, c) do { \
        __half2 p0 = __floats2half2_rn(ra[slot][0].x, ra[slot][0].y); \
        __half2 p1 = __floats2half2_rn(ra[slot][0].z, ra[slot][0].w); \
        __half2 p2 = __floats2half2_rn(ra[slot][1].x, ra[slot][1].y); \
        __half2 p3 = __floats2half2_rn(ra[slot][1].z, ra[slot][1].w); \
        uint32_t u0 = *reinterpret_cast<uint32_t*>(&p0); \
        uint32_t u1 = *reinterpret_cast<uint32_t*>(&p1); \
        uint32_t u2 = *reinterpret_cast<uint32_t*>(&p2); \
        uint32_t u3 = *reinterpret_cast<uint32_t*>(&p3); \
        asm volatile("st.shared.v4.b32 [%0], {%1,%2,%3,%4};" \
            :: "r"(sa + (stg) * SA), "r"(u0), "r"(u1), "r"(u2), "r"(u3) : "memory"); \
        uint4 og; og.x = u0; og.y = u1; og.z = u2; og.w = u3; \
        *reinterpret_cast<uint4*>(agout + (c) * 32) = og; \
    } while (0)

    uint32_t aoff[2], boff[2];
    {
        int arow = lane & 15, akb = lane >> 4;
        #pragma unroll
        for (int mt = 0; mt < 2; mt++)
            aoff[mt] = (uint32_t)(((wm + mt * 16 + arow) * 40 + akb * 8) * 2);
        int bn = (lane & 7) + ((lane >> 4) << 3), bkb = (lane >> 3) & 1;
        #pragma unroll
        for (int nt = 0; nt < 2; nt++)
            boff[nt] = (uint32_t)(((wn + nt * 16 + bn) * 40 + bkb * 8) * 2);
    }
    uint32_t asb = smaddr(As), bsb = smaddr(Bs);

    float acc[2][4][4];
    #pragma unroll
    for (int i = 0; i < 2; i++)
        #pragma unroll
        for (int j = 0; j < 4; j++)
            #pragma unroll
            for (int k = 0; k < 4; k++) acc[i][j][k] = 0.0f;

    // prologue: B stages 0..2 via cp.async; A chunks 0..2 via regs
    LDGA(0, 0); LDGA(1, 1);
    #pragma unroll
    for (int st = 0; st < 3; st++) {
        int k0 = st * 32;
        cp16(sb + st * SB, bpg + k0);
        cp16(sb + st * SB + 16, bpg + k0 + 8);
        cp_commit();
    }
    PUTA(0, 0, 0); LDGA(0, 2);
    PUTA(1, 1, 1); LDGA(1, 3);
    PUTA(2, 0, 2); LDGA(0, 4);
    // slots now: slot1 = chunk3, slot0 = chunk4

    int stage = 0;
    for (int s = 0; s < 16; s++) {
        cp_wait<2>();
        __syncthreads();
        uint32_t ab = asb + stage * SA;
        uint32_t bb = bsb + stage * SB;
        #pragma unroll
        for (int kk = 0; kk < 2; kk++) {
            uint32_t af[2][4], bq[2][4];
            ldsm4(af[0], ab + aoff[0] + kk * 32);
            ldsm4(af[1], ab + aoff[1] + kk * 32);
            ldsm4(bq[0], bb + boff[0] + kk * 32);
            ldsm4(bq[1], bb + boff[1] + kk * 32);
            #pragma unroll
            for (int mt = 0; mt < 2; mt++)
                #pragma unroll
                for (int j = 0; j < 4; j++)
                    mma16(acc[mt][j], af[mt], &bq[j >> 1][(j & 1) * 2]);
        }
        __syncthreads();
        if (s < 13) {
            PUTA(stage, (s + 3) & 1, s + 3);
            int k0 = (s + 3) * 32;
            cp16(sb + stage * SB, bpg + k0);
            cp16(sb + stage * SB + 16, bpg + k0 + 8);
        }
        if (s < 11) LDGA((s + 5) & 1, s + 5);
        cp_commit();
        stage++; if (stage == 3) stage = 0;
    }

    // epilogue: HW tanh + dot with wa; in-quad shuffle, then cross-n-warp reduce
    float ps[2][2] = {{0.0f, 0.0f}, {0.0f, 0.0f}};
    #pragma unroll
    for (int mt = 0; mt < 2; mt++) {
        #pragma unroll
        for (int nt = 0; nt < 4; nt++) {
            int c = wn + nt * 8 + 2 * (lane & 3);
            float a0 = addsh[c], a1 = addsh[c + 1];
            float w0 = wash[c], w1 = wash[c + 1];
            float t0 = tanh_ap(acc[mt][nt][0] + a0);
            float t1 = tanh_ap(acc[mt][nt][1] + a1);
            float t2 = tanh_ap(acc[mt][nt][2] + a0);
            float t3 = tanh_ap(acc[mt][nt][3] + a1);
            ps[mt][0] += t0 * w0 + t1 * w1;
            ps[mt][1] += t2 * w0 + t3 * w1;
        }
    }
    #pragma unroll
    for (int o = 1; o <= 2; o <<= 1) {
        ps[0][0] += __shfl_xor_sync(0xffffffff, ps[0][0], o);
        ps[0][1] += __shfl_xor_sync(0xffffffff, ps[0][1], o);
        ps[1][0] += __shfl_xor_sync(0xffffffff, ps[1][0], o);
        ps[1][1] += __shfl_xor_sync(0xffffffff, ps[1][1], o);
    }
    if ((lane & 3) == 0) {
        int wq = wid & 3;
        int lq = lane >> 2;
        #pragma unroll
        for (int mt = 0; mt < 2; mt++) {
            int r = wm + mt * 16 + lq;
            red[r * 5 + wq] = ps[mt][0];
            red[(r + 8) * 5 + wq] = ps[mt][1];
        }
    }
    __syncthreads();
    if (tid < 64) {
        g_scores[m0 + tid] = ba[0] + red[tid * 5] + red[tid * 5 + 1]
                           + red[tid * 5 + 2] + red[tid * 5 + 3];
    }
}

// ---------------- fused masked softmax + att_res (reads fp16 clip written by k_att_h)
__global__ void k_soft_attres(const int* __restrict__ mask) {
    __shared__ float sh[256];
    __shared__ float w[256];
    __shared__ float part[512];
    int b = blockIdx.x, t = threadIdx.x;
    float s = g_scores[b * LL + t];
    sh[t] = s;
    __syncthreads();
    for (int o = 128; o > 0; o >>= 1) {
        if (t < o) sh[t] = fmaxf(sh[t], sh[t + o]);
        __syncthreads();
    }
    float mx = sh[0];
    __syncthreads();
    float p = expf(s - mx);
    float pm = p * (float)mask[b * LL + t];
    sh[t] = pm;
    __syncthreads();
    for (int o = 128; o > 0; o >>= 1) {
        if (t < o) sh[t] += sh[t + o];
        __syncthreads();
    }
    float denom = sh[0];
    w[t] = pm / denom;
    __syncthreads();

    int half_ = t >> 7, tt = t & 127;
    const __half* cb = g_cliph + (size_t)b * LL * CD + (size_t)half_ * 128 * CD;
    const float* wl = w + half_ * 128;
    float a0 = 0.0f, a1 = 0.0f, a2 = 0.0f, a3 = 0.0f;
    #pragma unroll 4
    for (int l = 0; l < 128; l++) {
        float wv = wl[l];
        uint2 u = *reinterpret_cast<const uint2*>(cb + (size_t)l * CD + tt * 4);
        __half2 h0 = *reinterpret_cast<__half2*>(&u.x);
        __half2 h1 = *reinterpret_cast<__half2*>(&u.y);
        float2 f0 = __half22float2(h0);
        float2 f1 = __half22float2(h1);
        a0 += wv * f0.x; a1 += wv * f0.y; a2 += wv * f1.x; a3 += wv * f1.y;
    }
    if (half_) {
        part[tt * 4] = a0; part[tt * 4 + 1] = a1; part[tt * 4 + 2] = a2; part[tt * 4 + 3] = a3;
    }
    __syncthreads();
    if (!half_) {
        a0 += part[tt * 4]; a1 += part[tt * 4 + 1]; a2 += part[tt * 4 + 2]; a3 += part[tt * 4 + 3];
        __half2 h0 = __floats2half2_rn(a0, a1);
        __half2 h1 = __floats2half2_rn(a2, a3);
        uint2 o;
        o.x = *reinterpret_cast<uint32_t*>(&h0);
        o.y = *reinterpret_cast<uint32_t*>(&h1);
        *reinterpret_cast<uint2*>(&g_attresh[b * CD + tt * 4]) = o;
    }
}

// ---------------- launch ----------------
extern "C" void kernel_launch(void* const* d_in, const int* in_sizes, int n_in,
                              void* d_out, int out_size) {
    const float* xt      = (const float*)d_in[0];
    const float* video   = (const float*)d_in[1];
    const float* event   = (const float*)d_in[2];
    const float* clip    = (const float*)d_in[3];
    const int*   cmask   = (const int*)d_in[4];
    const float* state_h = (const float*)d_in[5];
    const float* state_c = (const float*)d_in[6];
    const float* w_ih0   = (const float*)d_in[7];
    const float* w_hh0   = (const float*)d_in[8];
    const float* b_ih0   = (const float*)d_in[9];
    const float* b_hh0   = (const float*)d_in[10];
    const float* w_ih1   = (const float*)d_in[11];
    const float* w_hh1   = (const float*)d_in[12];
    const float* b_ih1   = (const float*)d_in[13];
    const float* b_hh1   = (const float*)d_in[14];
    const float* w_ih2   = (const float*)d_in[15];
    const float* w_hh2   = (const float*)d_in[16];
    const float* b_ih2   = (const float*)d_in[17];
    const float* b_hh2   = (const float*)d_in[18];
    const float* wc      = (const float*)d_in[19];
    const float* bc      = (const float*)d_in[20];
    const float* wh      = (const float*)d_in[21];
    const float* bh      = (const float*)d_in[22];
    const float* wa      = (const float*)d_in[23];
    const float* ba      = (const float*)d_in[24];

    float* out = (float*)d_out;
    float* h2o = out;            // h2: [B,H]
    float* nh  = out + BH;       // new_h: 3 x [B,H]
    float* nc  = out + 4 * BH;   // new_c: 3 x [B,H]

    // weights + activations fp32->fp16 (clip handled inside k_att_h)
    k_f2h_all<<<F2H_ALL_BLOCKS, 256>>>(w_ih0, w_hh0, w_ih1, w_hh1, w_ih2, w_hh2,
                                       wc, xt, event,
                                       state_h, state_h + BH, state_h + 2 * BH);
    k_vbias<<<(G4H * 32) / 256, 256>>>(video, w_ih0, b_ih0, b_hh0);

    dim3 ggrid(G4H / 64, BB / 64);   // (32, 8)

    // layer 0
    k_gemm3_h<<<ggrid, 128>>>(0, b_ih0, b_hh0, /*bias_mode=*/1);
    k_lstm_act<<<BH / 256, 256>>>(state_c, nh, nc, nullptr, /*hsel=*/0);

    // layer 1
    k_gemm3_h<<<ggrid, 128>>>(1, b_ih1, b_hh1, 0);
    k_lstm_act<<<BH / 256, 256>>>(state_c + BH, nh + BH, nc + BH, nullptr, /*hsel=*/1);

    // attention (k_att_h also produces the fp16 clip copy for k_soft_attres)
    k_atth<<<BB, 128>>>(nh + BH, wh, bh);
    k_att_h<<<(BB * LL) / 64, 256>>>(clip, bc, wa, ba);
    k_soft_attres<<<BB, 256>>>(cmask);

    // layer 2
    k_gemm3_h<<<ggrid, 128>>>(2, b_ih2, b_hh2, 0);
    k_lstm_act<<<BH / 256, 256>>>(state_c + 2 * BH, nh + 2 * BH, nc + 2 * BH, h2o, /*hsel=*/2);
}